// round 5
// baseline (speedup 1.0000x reference)
#include <cuda_runtime.h>

#define N_SAMPLES   8192
#define N_CHANNELS  1024
#define N_COMP      4
#define THREADS     128          // 8 channels per thread
#define SPB         4            // samples per block (grid 2048 -> ~55 warps/SM)
#define CH          8

__global__ void __launch_bounds__(THREADS)
smf_kernel(const float* __restrict__ comp,      // [4, 1024]
           const float* __restrict__ contrib,   // [8192, 4]
           const float* __restrict__ shift,     // [8192, 4]
           float* __restrict__ out)             // [8192, 1024]
{
    // per-(sample,comp) params: {w0, w1, w2, bitcast(u2)}
    __shared__ __align__(16) float4 sP[SPB][N_COMP];

    const int tid   = threadIdx.x;
    const int i0    = tid * CH;
    const int sbase = blockIdx.x * SPB;

    // ---- precompute (SPB*4 = 16 threads, one per (s,k)) ----
    if (tid < SPB * N_COMP) {
        const int s = tid >> 2, k = tid & 3;
        const float sh = shift[(sbase + s) * N_COMP + k];
        const float cn = contrib[(sbase + s) * N_COMP + k];
        const int   fi = (int)floorf(sh);          // in [-4, 3]
        const int   g  = fi & ~1;                  // even window base in {-4,-2,0,2}
        const int   u2 = (g + 4) >> 1;             // in [0,3]
        const float x  = sh - (float)g;            // in [0, 2)
        // 3-tap weights: w_j = cn * max(0, 1 - |j - x|); exactly 2 are nonzero
        const float w0 = cn * fmaxf(0.0f, 1.0f - fabsf(0.0f - x));
        const float w1 = cn * fmaxf(0.0f, 1.0f - fabsf(1.0f - x));
        const float w2 = cn * fmaxf(0.0f, 1.0f - fabsf(2.0f - x));
        sP[s][k] = make_float4(w0, w1, w2, __int_as_float(u2));
    }

    // ---- register-resident window: cf[k][t] = comp[k, i0-4+t], t in [0,16) ----
    float cf[N_COMP][16];
    #pragma unroll
    for (int k = 0; k < N_COMP; k++) {
        #pragma unroll
        for (int q = 0; q < 4; q++) {
            const int j = i0 - 4 + 4 * q;          // float4-aligned
            float4 v = make_float4(0.f, 0.f, 0.f, 0.f);
            if (j >= 0 && j < N_CHANNELS)
                v = __ldg((const float4*)(comp + k * N_CHANNELS + j));
            cf[k][4*q+0] = v.x; cf[k][4*q+1] = v.y;
            cf[k][4*q+2] = v.z; cf[k][4*q+3] = v.w;
        }
    }
    __syncthreads();

    #pragma unroll
    for (int s = 0; s < SPB; s++) {
        float acc[CH];
        #pragma unroll
        for (int i = 0; i < CH; i++) acc[i] = 0.f;

        #pragma unroll
        for (int k = 0; k < N_COMP; k++) {
            const float4 p = sP[s][k];             // LDS.128 broadcast
            const float w0 = p.x, w1 = p.y, w2 = p.z;
            const int   u2 = __float_as_int(p.w);
            const bool  b1 = (u2 >= 2);            // shift window by 4 floats (1 ISETP)
            const bool  b0 = (u2 & 1);             // shift window by 2 floats

            float m[12];
            #pragma unroll
            for (int t = 0; t < 12; t++) m[t] = b1 ? cf[k][t + 4] : cf[k][t];
            float v[10];
            #pragma unroll
            for (int t = 0; t < 10; t++) v[t] = b0 ? m[t + 2] : m[t];

            #pragma unroll
            for (int i = 0; i < CH; i++)
                acc[i] += w0 * v[i] + w1 * v[i + 1] + w2 * v[i + 2];
        }

        float4* o4 = (float4*)out + (size_t)(sbase + s) * (N_CHANNELS / 4) + (i0 >> 2);
        o4[0] = make_float4(acc[0], acc[1], acc[2], acc[3]);
        o4[1] = make_float4(acc[4], acc[5], acc[6], acc[7]);
    }
}

extern "C" void kernel_launch(void* const* d_in, const int* in_sizes, int n_in,
                              void* d_out, int out_size)
{
    // inputs [8192,1024] (ignored), components [4,1024],
    // contributions [8192,4], shift [8192,4]
    const float* comp    = (const float*)d_in[1];
    const float* contrib = (const float*)d_in[2];
    const float* shift   = (const float*)d_in[3];
    float* out           = (float*)d_out;

    smf_kernel<<<N_SAMPLES / SPB, THREADS>>>(comp, contrib, shift, out);
}

// round 6
// speedup vs baseline: 1.2308x; 1.2308x over previous
#include <cuda_runtime.h>

#define NS       8192
#define NC       1024
#define NK       4
#define TILE     32            // channels per block
#define THREADS  256           // samples per block
#define PAD      4
#define WROW     48            // smem comp row stride (40 words used)
#define SROW     33            // staging row stride (32 + 1 pad) -> conflict-free

__global__ void __launch_bounds__(THREADS)
smf_kernel(const float* __restrict__ comp,      // [4, 1024]
           const float* __restrict__ contrib,   // [8192, 4]
           const float* __restrict__ shift,     // [8192, 4]
           float* __restrict__ out)             // [8192, 1024]
{
    __shared__ float sc[NK * WROW];             // comp window for this channel tile
    __shared__ float st[THREADS * SROW];        // staging: [sample][channel], pad 1

    const int tid  = threadIdx.x;
    const int tile = blockIdx.x & 31;           // 32 channel tiles
    const int grp  = blockIdx.x >> 5;           // 32 sample groups
    const int c0   = tile * TILE;
    const int s    = grp * THREADS + tid;       // this thread's sample

    // ---- fill comp window: rows [k][c0-4 .. c0+35], OOB = 0 ----
    if (tid < NK * 40) {
        const int k = tid / 40, w = tid - k * 40;
        const int j = c0 - PAD + w;
        sc[k * WROW + w] = (j >= 0 && j < NC) ? comp[k * NC + j] : 0.0f;
    }

    // ---- per-sample params (per-lane; no uniformity needed) ----
    const float4 sh4 = __ldg((const float4*)(shift   + s * NK));
    const float4 cn4 = __ldg((const float4*)(contrib + s * NK));
    const float shv[NK] = { sh4.x, sh4.y, sh4.z, sh4.w };
    const float cnv[NK] = { cn4.x, cn4.y, cn4.z, cn4.w };

    float a[NK], b[NK];
    int   base[NK];
    #pragma unroll
    for (int k = 0; k < NK; k++) {
        const float sh = shv[k];
        const float cn = cnv[k];
        const float ff = floorf(sh);
        int   fi = (int)ff;                     // in [-4, 4]
        float fr = sh - ff;
        if (fi > 3)  { fr += (float)(fi - 3); fi = 3; }   // shift == 4.0 edge
        if (fi < -4) { fi = -4; }
        b[k]    = cn * fr;                      // weight of tap fi+1
        a[k]    = cn - b[k];                    // cn*(1-fr)
        base[k] = k * WROW + fi + PAD;          // word offset of tap fi for i=0
    }
    __syncthreads();

    // ---- main loop: per channel i, gather 2 taps per k with running chain ----
    float t0[NK];
    #pragma unroll
    for (int k = 0; k < NK; k++) t0[k] = sc[base[k]];     // tap at i=0

    float* my = st + tid * SROW;
    #pragma unroll
    for (int i = 0; i < TILE; i++) {
        float acc = 0.0f;
        #pragma unroll
        for (int k = 0; k < NK; k++) {
            const float t1 = sc[base[k] + i + 1];          // 1-wf gather (<=9 banks)
            acc += a[k] * t0[k] + b[k] * t1;
            t0[k] = t1;                                    // reuse as next tap0
        }
        my[i] = acc;                                       // conflict-free STS
    }
    __syncthreads();

    // ---- coalesced tile store: warp covers 4 samples x 8 float4s each ----
    #pragma unroll
    for (int j = 0; j < (THREADS * TILE / 4) / THREADS; j++) {   // 8 iters
        const int flat = j * THREADS + tid;     // 0..2047
        const int sl   = flat >> 3;             // local sample 0..255
        const int q    = flat & 7;              // float4 index within tile
        const float* r = st + sl * SROW + q * 4;
        const float4 v = make_float4(r[0], r[1], r[2], r[3]);   // conflict-free
        ((float4*)out)[(size_t)(grp * THREADS + sl) * (NC / 4) + (c0 >> 2) + q] = v;
    }
}

extern "C" void kernel_launch(void* const* d_in, const int* in_sizes, int n_in,
                              void* d_out, int out_size)
{
    // inputs [8192,1024] (ignored), components [4,1024],
    // contributions [8192,4], shift [8192,4]
    const float* comp    = (const float*)d_in[1];
    const float* contrib = (const float*)d_in[2];
    const float* shift   = (const float*)d_in[3];
    float* out           = (float*)d_out;

    smf_kernel<<<32 * 32, THREADS>>>(comp, contrib, shift, out);   // 1024 blocks
}

// round 7
// speedup vs baseline: 1.2549x; 1.0196x over previous
#include <cuda_runtime.h>

#define NS       8192
#define NC       1024
#define NK       4
#define TILE     32            // channels per block tile
#define THREADS  128
#define SPT      2             // samples per thread (sequential rounds)
#define PAD      4
#define WROW     48            // comp row stride (40 words used, even -> 8B align)
#define SROW     36            // staging row stride in words (16B-aligned, bank-spread)

__global__ void __launch_bounds__(THREADS)
smf_kernel(const float* __restrict__ comp,      // [4, 1024]
           const float* __restrict__ contrib,   // [8192, 4]
           const float* __restrict__ shift,     // [8192, 4]
           float* __restrict__ out)             // [8192, 1024]
{
    __shared__ __align__(16) float sc[NK * WROW];        // comp window
    __shared__ __align__(16) float st[THREADS * SROW];   // staging (reused per round)

    const int tid  = threadIdx.x;
    const int tile = blockIdx.x & 31;
    const int grp  = blockIdx.x >> 5;
    const int c0   = tile * TILE;

    // ---- fill comp window rows [k][c0-4 .. c0+35], OOB = 0 ----
    for (int idx = tid; idx < NK * 40; idx += THREADS) {
        const int k = idx / 40, w = idx - k * 40;
        const int j = c0 - PAD + w;
        sc[k * WROW + w] = (j >= 0 && j < NC) ? comp[k * NC + j] : 0.0f;
    }
    __syncthreads();

    #pragma unroll
    for (int r = 0; r < SPT; r++) {
        const int s = grp * (THREADS * SPT) + r * THREADS + tid;

        const float4 sh4 = __ldg((const float4*)(shift   + s * NK));
        const float4 cn4 = __ldg((const float4*)(contrib + s * NK));
        const float shv[NK] = { sh4.x, sh4.y, sh4.z, sh4.w };
        const float cnv[NK] = { cn4.x, cn4.y, cn4.z, cn4.w };

        float w0[NK], w1[NK], w2[NK];
        int   base[NK];
        #pragma unroll
        for (int k = 0; k < NK; k++) {
            const float sh = shv[k];
            const float cn = cnv[k];
            int fi = (int)floorf(sh);
            fi = max(-4, min(3, fi));            // handles shift == 4.0 edge too
            const int   g = fi & ~1;             // even window base in {-4,-2,0,2}
            const float x = sh - (float)g;       // in [0, 2]
            // 3-tap weights, constant across channels (window slides with i)
            w0[k] = cn * fmaxf(0.0f, 1.0f - fabsf(x));
            w1[k] = cn * fmaxf(0.0f, 1.0f - fabsf(1.0f - x));
            w2[k] = cn * fmaxf(0.0f, 1.0f - fabsf(2.0f - x));
            base[k] = k * WROW + g + PAD;        // even -> LDS.64 aligned
        }

        // rolling float2 per k
        float2 u[NK];
        #pragma unroll
        for (int k = 0; k < NK; k++) u[k] = *(const float2*)&sc[base[k]];

        float4* myst = (float4*)(st + tid * SROW);
        float4 buf;
        #pragma unroll
        for (int ip = 0; ip < TILE / 2; ip++) {  // channels 2ip, 2ip+1
            float a0 = 0.f, a1 = 0.f;
            #pragma unroll
            for (int k = 0; k < NK; k++) {
                const float2 v = *(const float2*)&sc[base[k] + 2 * ip + 2];
                a0 += w0[k] * u[k].x + w1[k] * u[k].y + w2[k] * v.x;
                a1 += w0[k] * u[k].y + w1[k] * v.x  + w2[k] * v.y;
                u[k] = v;
            }
            if (ip & 1) { buf.z = a0; buf.w = a1; myst[ip >> 1] = buf; }
            else        { buf.x = a0; buf.y = a1; }
        }
        __syncthreads();

        // ---- coalesced tile store: 128 samples x 8 float4 each ----
        #pragma unroll
        for (int j2 = 0; j2 < 8; j2++) {
            const int flat = j2 * THREADS + tid;  // 0..1023
            const int sl   = flat >> 3;           // local sample 0..127
            const int q    = flat & 7;
            const float4 v = ((const float4*)st)[sl * (SROW / 4) + q];
            ((float4*)out)[(size_t)(grp * (THREADS * SPT) + r * THREADS + sl) * (NC / 4)
                           + (c0 >> 2) + q] = v;
        }
        __syncthreads();
    }
}

extern "C" void kernel_launch(void* const* d_in, const int* in_sizes, int n_in,
                              void* d_out, int out_size)
{
    // inputs [8192,1024] (ignored), components [4,1024],
    // contributions [8192,4], shift [8192,4]
    const float* comp    = (const float*)d_in[1];
    const float* contrib = (const float*)d_in[2];
    const float* shift   = (const float*)d_in[3];
    float* out           = (float*)d_out;

    smf_kernel<<<32 * 32, THREADS>>>(comp, contrib, shift, out);   // 1024 blocks
}